// round 14
// baseline (speedup 1.0000x reference)
#include <cuda_runtime.h>
#include <cuda_fp16.h>
#include <math.h>
#include <stdint.h>

#define NQ 8192
#define DQ 128
#define EQ 262144
#define EDIM 50
#define HID 32

// ---------------- scratch (device globals: no allocation allowed) ----------------
__device__ float   g_scores [(size_t)NQ * NQ];    // 256 MiB fp32 logits
__device__ __half  g_attn   [(size_t)NQ * NQ];    // 128 MiB fp16 probabilities
__device__ __half  g_ab     [(size_t)NQ * 256];   // [N][a|b], K=256 (fp16)
__device__ __half  g_mpT    [(size_t)256 * NQ];   // [mag|phase]^T (fp16)

__device__ __forceinline__ uint32_t smem_u32(const void* p) {
    uint32_t a;
    asm("{ .reg .u64 t; cvta.to.shared.u64 t, %1; cvt.u32.u64 %0, t; }" : "=r"(a) : "l"(p));
    return a;
}
__device__ __forceinline__ void cp_async16(void* sdst, const void* gsrc) {
    unsigned s = (unsigned)__cvta_generic_to_shared(sdst);
    asm volatile("cp.async.cg.shared.global [%0], [%1], 16;\n" :: "r"(s), "l"(gsrc));
}
#define CP_COMMIT() asm volatile("cp.async.commit_group;\n" ::: "memory")

__device__ __forceinline__ void ldmx4(uint32_t* r, uint32_t addr) {
    asm volatile("ldmatrix.sync.aligned.m8n8.x4.shared.b16 {%0,%1,%2,%3}, [%4];"
                 : "=r"(r[0]), "=r"(r[1]), "=r"(r[2]), "=r"(r[3]) : "r"(addr));
}

// ---------------- K1: prep a,b / mpT (fp16) + zero the output buffer -------
__global__ void prep_kernel(const float* __restrict__ mag, const float* __restrict__ phase,
                            float* __restrict__ out) {
    int idx = blockIdx.x * blockDim.x + threadIdx.x;   // < N*D (= 1M)
    int i = idx >> 7;
    int d = idx & 127;
    float m = mag[idx];
    float p = phase[idx];
    float s, c;
    __sincosf(p, &s, &c);
    g_ab[(size_t)i * 256 + d]         = __float2half_rn(m * c);
    g_ab[(size_t)i * 256 + 128 + d]   = __float2half_rn(m * s);
    g_mpT[(size_t)d * NQ + i]         = __float2half_rn(m);
    g_mpT[(size_t)(128 + d) * NQ + i] = __float2half_rn(p);
    // zero out[2M]: 2 floats per thread
    *(float2*)&out[(size_t)idx * 2] = make_float2(0.f, 0.f);
}

// ---------------- GEMM (fp16, fp32 accum): BM=128, BK=64, 8 warps, m16n8k16 ------
// ldmatrix.x4 fragments, 1 MMA term.
// MODE 0: BN=128, warp tile 64x32, occ=2, 3-stage cp.async pipeline.
//         A=g_ab[bm], B=g_ab[bn]; K=256 (nit=4), C=g_scores*scale; SYMMETRIC upper tiles.
// MODE 1: BN=256, warp tile 64x64, occ=1, 2-stage pipeline. A=g_attn[bm], B=g_mpT;
//         K=8192 split-K z=8 (nit=16), atomicAdd into Cout.
#define TSTRIDE 72

template <int MODE>
__global__ __launch_bounds__(256, (MODE == 0) ? 2 : 1)
void gemm_kernel(float* __restrict__ Cout, float scale) {
    extern __shared__ __align__(16) __half dsm[];

    constexpr int NB   = (MODE == 0) ? 128 : 256;      // B rows per tile
    constexpr int NI   = (MODE == 0) ? 4 : 8;          // n sub-tiles per warp
    constexpr int NSTG = (MODE == 0) ? 3 : 2;          // pipeline stages
    constexpr int ATSZ = 128 * TSTRIDE;                // A tile elems
    constexpr int BTSZ = NB * TSTRIDE;                 // B tile elems
    constexpr int STG  = ATSZ + BTSZ;                  // stage elems

    const int bm = blockIdx.y, bn = blockIdx.x;
    if (MODE == 0 && bn < bm) return;   // symmetric: upper-triangle tiles only

    const int K = (MODE == 0) ? 256 : NQ;
    const __half* T0 = (MODE == 0) ? (g_ab  + (size_t)bm * 128 * K)
                                   : (g_attn + (size_t)bm * 128 * K);
    const __half* T1 = (MODE == 0) ? (g_ab  + (size_t)bn * 128 * K) : g_mpT;

    const int tid = threadIdx.x;
    const int warp = tid >> 5, lane = tid & 31;
    const int wm = warp >> 2, wn = warp & 3;
    const int g = lane >> 2, q = lane & 3;

    float acc[4][NI][4];
#pragma unroll
    for (int mi = 0; mi < 4; mi++)
#pragma unroll
        for (int ni = 0; ni < NI; ni++)
#pragma unroll
            for (int r = 0; r < 4; r++) acc[mi][ni][r] = 0.f;

    const int kbeg = (MODE == 0) ? 0 : blockIdx.z * (NQ / 8);
    const int nit = ((MODE == 0) ? 256 : NQ / 8) / 64;

    // ldmatrix per-lane byte offsets (row stride 144 B)
    const int xr = lane & 7;
    const int xb = (lane >> 3) & 1;
    const int xk = (lane >> 4) & 1;
    uint32_t aoff[4], boff[NI / 2];
#pragma unroll
    for (int mi = 0; mi < 4; mi++)
        aoff[mi] = (uint32_t)((wm * 64 + mi * 16 + xb * 8 + xr) * (TSTRIDE * 2) + xk * 16);
#pragma unroll
    for (int pi = 0; pi < NI / 2; pi++)
        boff[pi] = (uint32_t)((wn * (NI * 8) + pi * 16 + xb * 8 + xr) * (TSTRIDE * 2) + xk * 16);

    const uint32_t smbase = smem_u32(dsm);

    // Fill stage slot (IT % NSTG). A: 128x8 chunks(16B); B: NBx8 chunks.
#define PREFETCH(IT)                                                             \
    do {                                                                         \
        int k0_ = kbeg + (IT) * 64;                                              \
        __half* d_ = dsm + ((IT) % NSTG) * STG;                                  \
        _Pragma("unroll")                                                        \
        for (int i_ = 0; i_ < 4; i_++) {                                         \
            int u_ = tid + i_ * 256;                                             \
            int r_ = u_ >> 3, c_ = (u_ & 7) * 8;                                 \
            cp_async16(d_ + r_ * TSTRIDE + c_, T0 + (size_t)r_ * K + k0_ + c_);  \
        }                                                                        \
        _Pragma("unroll")                                                        \
        for (int i_ = 0; i_ < NB / 32; i_++) {                                   \
            int u_ = tid + i_ * 256;                                             \
            int r_ = u_ >> 3, c_ = (u_ & 7) * 8;                                 \
            cp_async16(d_ + ATSZ + r_ * TSTRIDE + c_,                            \
                       T1 + (size_t)r_ * K + k0_ + c_);                          \
        }                                                                        \
    } while (0)

#pragma unroll
    for (int pf = 0; pf < NSTG - 1; pf++) {
        PREFETCH(pf);
        CP_COMMIT();
    }

    for (int it = 0; it < nit; it++) {
        if (it + NSTG - 1 < nit) PREFETCH(it + NSTG - 1);
        CP_COMMIT();
        // wait until stage `it` is complete (NSTG-1 newer groups may stay pending)
        if constexpr (MODE == 0)
            asm volatile("cp.async.wait_group 2;\n" ::: "memory");
        else
            asm volatile("cp.async.wait_group 1;\n" ::: "memory");
        __syncthreads();

        const uint32_t S0 = smbase + (uint32_t)(it % NSTG) * STG * 2;   // bytes
        const uint32_t S1 = S0 + ATSZ * 2;

#pragma unroll
        for (int kk = 0; kk < 4; kk++) {
            const uint32_t kb = kk * 32;
            uint32_t ra[4][4], rb[NI / 2][4];
#pragma unroll
            for (int mi = 0; mi < 4; mi++) ldmx4(ra[mi], S0 + aoff[mi] + kb);
#pragma unroll
            for (int pi = 0; pi < NI / 2; pi++) ldmx4(rb[pi], S1 + boff[pi] + kb);

#pragma unroll
            for (int mi = 0; mi < 4; mi++)
#pragma unroll
                for (int ni = 0; ni < NI; ni++) {
                    const int pi = ni >> 1, h = ni & 1;
                    asm volatile(
                        "mma.sync.aligned.m16n8k16.row.col.f32.f16.f16.f32 "
                        "{%0,%1,%2,%3}, {%4,%5,%6,%7}, {%8,%9}, {%0,%1,%2,%3};\n"
                        : "+f"(acc[mi][ni][0]), "+f"(acc[mi][ni][1]),
                          "+f"(acc[mi][ni][2]), "+f"(acc[mi][ni][3])
                        : "r"(ra[mi][0]), "r"(ra[mi][1]), "r"(ra[mi][2]), "r"(ra[mi][3]),
                          "r"(rb[pi][h]), "r"(rb[pi][h + 2]));
                }
        }
        __syncthreads();
    }
#undef PREFETCH

    // epilogue
#pragma unroll
    for (int mi = 0; mi < 4; mi++) {
        int r0 = bm * 128 + wm * 64 + mi * 16 + g;
#pragma unroll
        for (int ni = 0; ni < NI; ni++) {
            if (MODE == 0) {
                int c0 = bn * 128 + wn * 32 + ni * 8 + 2 * q;
                float v0 = acc[mi][ni][0] * scale, v1 = acc[mi][ni][1] * scale;
                float v2 = acc[mi][ni][2] * scale, v3 = acc[mi][ni][3] * scale;
                *(float2*)&g_scores[(size_t)r0 * NQ + c0]       = make_float2(v0, v1);
                *(float2*)&g_scores[(size_t)(r0 + 8) * NQ + c0] = make_float2(v2, v3);
                if (bm != bn) {   // symmetric mirror
                    g_scores[(size_t)c0 * NQ + r0]           = v0;
                    g_scores[(size_t)(c0 + 1) * NQ + r0]     = v1;
                    g_scores[(size_t)c0 * NQ + r0 + 8]       = v2;
                    g_scores[(size_t)(c0 + 1) * NQ + r0 + 8] = v3;
                }
            } else {
                int c0 = wn * 64 + ni * 8 + 2 * q;    // 0..255
                size_t base = (c0 < 128) ? 0 : ((size_t)NQ * 128 - 128);
                atomicAdd(&Cout[base + (size_t)r0 * 128 + c0], acc[mi][ni][0]);
                atomicAdd(&Cout[base + (size_t)r0 * 128 + c0 + 1], acc[mi][ni][1]);
                atomicAdd(&Cout[base + (size_t)(r0 + 8) * 128 + c0], acc[mi][ni][2]);
                atomicAdd(&Cout[base + (size_t)(r0 + 8) * 128 + c0 + 1], acc[mi][ni][3]);
            }
        }
    }
}

// ---------------- K3: edge bias MLP + scatter-add onto scores (edge_index is int32) ----
__global__ void bias_kernel(const int* __restrict__ ei, const float* __restrict__ rbf,
                            const float* __restrict__ W1, const float* __restrict__ b1,
                            const float* __restrict__ W2, const float* __restrict__ b2) {
    __shared__ float sW1[EDIM * HID];
    __shared__ float sb1[HID], sW2[HID];
    __shared__ float sb2;
    for (int t = threadIdx.x; t < EDIM * HID; t += blockDim.x) sW1[t] = W1[t];
    if (threadIdx.x < HID) { sb1[threadIdx.x] = b1[threadIdx.x]; sW2[threadIdx.x] = W2[threadIdx.x]; }
    if (threadIdx.x == 0) sb2 = b2[0];
    __syncthreads();

    int e = blockIdx.x * blockDim.x + threadIdx.x;
    if (e >= EQ) return;

    float h[HID];
#pragma unroll
    for (int j = 0; j < HID; j++) h[j] = sb1[j];
    const float* r = rbf + (size_t)e * EDIM;
    for (int k = 0; k < EDIM; k++) {
        float rv = __ldg(&r[k]);
#pragma unroll
        for (int j = 0; j < HID; j++) h[j] = fmaf(rv, sW1[k * HID + j], h[j]);
    }
    float bias = sb2;
#pragma unroll
    for (int j = 0; j < HID; j++) {
        float x = h[j];
        float si = x / (1.f + __expf(-x));   // SiLU
        bias = fmaf(si, sW2[j], bias);
    }
    int i  = ei[e];
    int jn = ei[EQ + e];
    atomicAdd(&g_scores[(size_t)i * NQ + jn], bias);
}

// ---------------- K4: row softmax, register-resident ----------------
__global__ __launch_bounds__(256)
void softmax_kernel() {
    __shared__ float red[8];
    const int row = blockIdx.x, tid = threadIdx.x;
    const float4* src = (const float4*)(g_scores + (size_t)row * NQ);

    float4 v[8];
    float m = -1e30f;
#pragma unroll
    for (int i = 0; i < 8; i++) {
        v[i] = src[tid + i * 256];
        m = fmaxf(m, fmaxf(fmaxf(v[i].x, v[i].y), fmaxf(v[i].z, v[i].w)));
    }
#pragma unroll
    for (int o = 16; o; o >>= 1) m = fmaxf(m, __shfl_xor_sync(0xffffffffu, m, o));
    if ((tid & 31) == 0) red[tid >> 5] = m;
    __syncthreads();
    float bm = red[0];
#pragma unroll
    for (int w = 1; w < 8; w++) bm = fmaxf(bm, red[w]);
    __syncthreads();

    float sum = 0.f;
#pragma unroll
    for (int i = 0; i < 8; i++) {
        v[i].x = __expf(v[i].x - bm); v[i].y = __expf(v[i].y - bm);
        v[i].z = __expf(v[i].z - bm); v[i].w = __expf(v[i].w - bm);
        sum += v[i].x + v[i].y + v[i].z + v[i].w;
    }
#pragma unroll
    for (int o = 16; o; o >>= 1) sum += __shfl_xor_sync(0xffffffffu, sum, o);
    if ((tid & 31) == 0) red[tid >> 5] = sum;
    __syncthreads();
    float tot = 0.f;
#pragma unroll
    for (int w = 0; w < 8; w++) tot += red[w];
    const float inv = 1.f / tot;

    uint2* dst = (uint2*)(g_attn + (size_t)row * NQ);
#pragma unroll
    for (int i = 0; i < 8; i++) {
        __half2 lo = __floats2half2_rn(v[i].x * inv, v[i].y * inv);
        __half2 hi = __floats2half2_rn(v[i].z * inv, v[i].w * inv);
        uint2 o;
        o.x = *(unsigned*)&lo;
        o.y = *(unsigned*)&hi;
        dst[tid + i * 256] = o;
    }
}

// ---------------- launch ----------------
extern "C" void kernel_launch(void* const* d_in, const int* in_sizes, int n_in,
                              void* d_out, int out_size) {
    const float* mag   = (const float*)d_in[0];
    const float* phase = (const float*)d_in[1];
    const int*   ei    = (const int*)d_in[2];
    const float* rbf   = (const float*)d_in[3];
    const float* W1    = (const float*)d_in[4];
    const float* b1    = (const float*)d_in[5];
    const float* W2    = (const float*)d_in[6];
    const float* b2    = (const float*)d_in[7];
    float*       out   = (float*)d_out;

    const float inv_sqrt_d = 0.08838834764831843f;   // 1/sqrt(128)
    const int smem0 = 3 * (128 + 128) * TSTRIDE * (int)sizeof(__half);   // 110592
    const int smem1 = 2 * (128 + 256) * TSTRIDE * (int)sizeof(__half);   // 110592

    cudaFuncSetAttribute(gemm_kernel<0>, cudaFuncAttributeMaxDynamicSharedMemorySize, smem0);
    cudaFuncSetAttribute(gemm_kernel<1>, cudaFuncAttributeMaxDynamicSharedMemorySize, smem1);

    prep_kernel<<<(NQ * DQ) / 256, 256>>>(mag, phase, out);
    gemm_kernel<0><<<dim3(NQ / 128, NQ / 128), 256, smem0>>>(nullptr, inv_sqrt_d);
    bias_kernel<<<EQ / 256, 256>>>(ei, rbf, W1, b1, W2, b2);
    softmax_kernel<<<NQ, 256>>>();
    gemm_kernel<1><<<dim3(1, NQ / 128, 8), 256, smem1>>>(out, 1.0f);
}

// round 17
// speedup vs baseline: 1.0457x; 1.0457x over previous
#include <cuda_runtime.h>
#include <cuda_fp16.h>
#include <math.h>
#include <stdint.h>

#define NQ 8192
#define DQ 128
#define EQ 262144
#define EDIM 50
#define HID 32

// ---------------- scratch (device globals: no allocation allowed) ----------------
__device__ float   g_scores [(size_t)NQ * NQ];    // 256 MiB fp32 logits
__device__ __half  g_attn   [(size_t)NQ * NQ];    // 128 MiB fp16 probabilities
__device__ __half  g_ab     [(size_t)NQ * 256];   // [N][a|b], K=256 (fp16)
__device__ __half  g_mpT    [(size_t)256 * NQ];   // [mag|phase]^T (fp16)

__device__ __forceinline__ uint32_t smem_u32(const void* p) {
    uint32_t a;
    asm("{ .reg .u64 t; cvta.to.shared.u64 t, %1; cvt.u32.u64 %0, t; }" : "=r"(a) : "l"(p));
    return a;
}
__device__ __forceinline__ void cp_async16(void* sdst, const void* gsrc) {
    unsigned s = (unsigned)__cvta_generic_to_shared(sdst);
    asm volatile("cp.async.cg.shared.global [%0], [%1], 16;\n" :: "r"(s), "l"(gsrc));
}
#define CP_COMMIT() asm volatile("cp.async.commit_group;\n" ::: "memory")
#define CP_WAIT1()  asm volatile("cp.async.wait_group 1;\n" ::: "memory")

__device__ __forceinline__ void ldmx4(uint32_t* r, uint32_t addr) {
    asm volatile("ldmatrix.sync.aligned.m8n8.x4.shared.b16 {%0,%1,%2,%3}, [%4];"
                 : "=r"(r[0]), "=r"(r[1]), "=r"(r[2]), "=r"(r[3]) : "r"(addr));
}

// ---------------- K1: prep a,b / mpT (fp16) + zero the output buffer -------
__global__ void prep_kernel(const float* __restrict__ mag, const float* __restrict__ phase,
                            float* __restrict__ out) {
    int idx = blockIdx.x * blockDim.x + threadIdx.x;   // < N*D (= 1M)
    int i = idx >> 7;
    int d = idx & 127;
    float m = mag[idx];
    float p = phase[idx];
    float s, c;
    __sincosf(p, &s, &c);
    g_ab[(size_t)i * 256 + d]         = __float2half_rn(m * c);
    g_ab[(size_t)i * 256 + 128 + d]   = __float2half_rn(m * s);
    g_mpT[(size_t)d * NQ + i]         = __float2half_rn(m);
    g_mpT[(size_t)(128 + d) * NQ + i] = __float2half_rn(p);
    *(float2*)&out[(size_t)idx * 2] = make_float2(0.f, 0.f);
}

// ---------------- GEMM (fp16, fp32 accum): BM=128, BK=64, 8 warps, m16n8k16 ------
// cp.async 2-stage double buffer, ldmatrix.x4 fragments, 1 MMA term.
// MODE 0: BN=128, warp tile 64x32, occ=2. A=g_ab[bm], B=g_ab[bn]; K=256,
//         C=g_scores*scale; SYMMETRIC upper tiles + mirror.
// MODE 1: BN=256, warp tile 64x64, occ=1, kk-software-pipelined fragments.
//         A=g_attn[bm], B=g_mpT; K=8192 split-K z=4, atomicAdd into Cout.
#define TSTRIDE 72

template <int MODE>
__global__ __launch_bounds__(256, (MODE == 0) ? 2 : 1)
void gemm_kernel(float* __restrict__ Cout, float scale) {
    extern __shared__ __align__(16) __half dsm[];

    constexpr int NB   = (MODE == 0) ? 128 : 256;      // B rows per tile
    constexpr int NI   = (MODE == 0) ? 4 : 8;          // n sub-tiles per warp
    constexpr int ATSZ = 128 * TSTRIDE;                // A tile elems
    constexpr int BTSZ = NB * TSTRIDE;                 // B tile elems
    constexpr int STG  = ATSZ + BTSZ;                  // stage elems

    const int bm = blockIdx.y, bn = blockIdx.x;
    if (MODE == 0 && bn < bm) return;   // symmetric: upper-triangle tiles only

    const int K = (MODE == 0) ? 256 : NQ;
    const __half* T0 = (MODE == 0) ? (g_ab  + (size_t)bm * 128 * K)
                                   : (g_attn + (size_t)bm * 128 * K);
    const __half* T1 = (MODE == 0) ? (g_ab  + (size_t)bn * 128 * K) : g_mpT;

    const int tid = threadIdx.x;
    const int warp = tid >> 5, lane = tid & 31;
    const int wm = warp >> 2, wn = warp & 3;
    const int g = lane >> 2, q = lane & 3;

    float acc[4][NI][4];
#pragma unroll
    for (int mi = 0; mi < 4; mi++)
#pragma unroll
        for (int ni = 0; ni < NI; ni++)
#pragma unroll
            for (int r = 0; r < 4; r++) acc[mi][ni][r] = 0.f;

    const int kbeg = (MODE == 0) ? 0 : blockIdx.z * (NQ / 4);
    const int nit = ((MODE == 0) ? 256 : NQ / 4) / 64;

    // ldmatrix per-lane byte offsets (row stride 144 B)
    const int xr = lane & 7;
    const int xb = (lane >> 3) & 1;
    const int xk = (lane >> 4) & 1;
    uint32_t aoff[4], boff[NI / 2];
#pragma unroll
    for (int mi = 0; mi < 4; mi++)
        aoff[mi] = (uint32_t)((wm * 64 + mi * 16 + xb * 8 + xr) * (TSTRIDE * 2) + xk * 16);
#pragma unroll
    for (int pi = 0; pi < NI / 2; pi++)
        boff[pi] = (uint32_t)((wn * (NI * 8) + pi * 16 + xb * 8 + xr) * (TSTRIDE * 2) + xk * 16);

    const uint32_t smbase = smem_u32(dsm);

#define PREFETCH(IT, ST)                                                         \
    do {                                                                         \
        int k0_ = kbeg + (IT) * 64;                                              \
        __half* d_ = dsm + (ST) * STG;                                           \
        _Pragma("unroll")                                                        \
        for (int i_ = 0; i_ < 4; i_++) {                                         \
            int u_ = tid + i_ * 256;                                             \
            int r_ = u_ >> 3, c_ = (u_ & 7) * 8;                                 \
            cp_async16(d_ + r_ * TSTRIDE + c_, T0 + (size_t)r_ * K + k0_ + c_);  \
        }                                                                        \
        _Pragma("unroll")                                                        \
        for (int i_ = 0; i_ < NB / 32; i_++) {                                   \
            int u_ = tid + i_ * 256;                                             \
            int r_ = u_ >> 3, c_ = (u_ & 7) * 8;                                 \
            cp_async16(d_ + ATSZ + r_ * TSTRIDE + c_,                            \
                       T1 + (size_t)r_ * K + k0_ + c_);                          \
        }                                                                        \
    } while (0)

    PREFETCH(0, 0);
    CP_COMMIT();

    for (int it = 0; it < nit; it++) {
        if (it + 1 < nit) PREFETCH(it + 1, (it + 1) & 1);
        CP_COMMIT();
        CP_WAIT1();
        __syncthreads();

        const uint32_t S0 = smbase + (uint32_t)(it & 1) * STG * 2;   // bytes
        const uint32_t S1 = S0 + ATSZ * 2;

        if constexpr (MODE == 0) {
            // plain kk loop (keeps regs under the occ-2 cap)
#pragma unroll
            for (int kk = 0; kk < 4; kk++) {
                const uint32_t kb = kk * 32;
                uint32_t ra[4][4], rb[NI / 2][4];
#pragma unroll
                for (int mi = 0; mi < 4; mi++) ldmx4(ra[mi], S0 + aoff[mi] + kb);
#pragma unroll
                for (int pi = 0; pi < NI / 2; pi++) ldmx4(rb[pi], S1 + boff[pi] + kb);
#pragma unroll
                for (int mi = 0; mi < 4; mi++)
#pragma unroll
                    for (int ni = 0; ni < NI; ni++) {
                        const int pi = ni >> 1, h = ni & 1;
                        asm volatile(
                            "mma.sync.aligned.m16n8k16.row.col.f32.f16.f16.f32 "
                            "{%0,%1,%2,%3}, {%4,%5,%6,%7}, {%8,%9}, {%0,%1,%2,%3};\n"
                            : "+f"(acc[mi][ni][0]), "+f"(acc[mi][ni][1]),
                              "+f"(acc[mi][ni][2]), "+f"(acc[mi][ni][3])
                            : "r"(ra[mi][0]), "r"(ra[mi][1]), "r"(ra[mi][2]), "r"(ra[mi][3]),
                              "r"(rb[pi][h]), "r"(rb[pi][h + 2]));
                    }
            }
        } else {
            // software-pipelined kk loop: ldmatrix for kk+1 issued before MMAs of kk
            uint32_t raA[4][4], rbA[NI / 2][4], raB[4][4], rbB[NI / 2][4];
#pragma unroll
            for (int mi = 0; mi < 4; mi++) ldmx4(raA[mi], S0 + aoff[mi]);
#pragma unroll
            for (int pi = 0; pi < NI / 2; pi++) ldmx4(rbA[pi], S1 + boff[pi]);
#pragma unroll
            for (int kk = 0; kk < 4; kk++) {
                uint32_t (*cra)[4] = (kk & 1) ? raB : raA;
                uint32_t (*crb)[4] = (kk & 1) ? rbB : rbA;
                uint32_t (*nra)[4] = (kk & 1) ? raA : raB;
                uint32_t (*nrb)[4] = (kk & 1) ? rbA : rbB;
                if (kk < 3) {
                    const uint32_t kb = (kk + 1) * 32;
#pragma unroll
                    for (int mi = 0; mi < 4; mi++) ldmx4(nra[mi], S0 + aoff[mi] + kb);
#pragma unroll
                    for (int pi = 0; pi < NI / 2; pi++) ldmx4(nrb[pi], S1 + boff[pi] + kb);
                }
#pragma unroll
                for (int mi = 0; mi < 4; mi++)
#pragma unroll
                    for (int ni = 0; ni < NI; ni++) {
                        const int pi = ni >> 1, h = ni & 1;
                        asm volatile(
                            "mma.sync.aligned.m16n8k16.row.col.f32.f16.f16.f32 "
                            "{%0,%1,%2,%3}, {%4,%5,%6,%7}, {%8,%9}, {%0,%1,%2,%3};\n"
                            : "+f"(acc[mi][ni][0]), "+f"(acc[mi][ni][1]),
                              "+f"(acc[mi][ni][2]), "+f"(acc[mi][ni][3])
                            : "r"(cra[mi][0]), "r"(cra[mi][1]), "r"(cra[mi][2]), "r"(cra[mi][3]),
                              "r"(crb[pi][h]), "r"(crb[pi][h + 2]));
                    }
            }
        }
        __syncthreads();
    }
#undef PREFETCH

    // epilogue
#pragma unroll
    for (int mi = 0; mi < 4; mi++) {
        int r0 = bm * 128 + wm * 64 + mi * 16 + g;
#pragma unroll
        for (int ni = 0; ni < NI; ni++) {
            if (MODE == 0) {
                int c0 = bn * 128 + wn * 32 + ni * 8 + 2 * q;
                float v0 = acc[mi][ni][0] * scale, v1 = acc[mi][ni][1] * scale;
                float v2 = acc[mi][ni][2] * scale, v3 = acc[mi][ni][3] * scale;
                *(float2*)&g_scores[(size_t)r0 * NQ + c0]       = make_float2(v0, v1);
                *(float2*)&g_scores[(size_t)(r0 + 8) * NQ + c0] = make_float2(v2, v3);
                if (bm != bn) {   // symmetric mirror
                    g_scores[(size_t)c0 * NQ + r0]           = v0;
                    g_scores[(size_t)(c0 + 1) * NQ + r0]     = v1;
                    g_scores[(size_t)c0 * NQ + r0 + 8]       = v2;
                    g_scores[(size_t)(c0 + 1) * NQ + r0 + 8] = v3;
                }
            } else {
                int c0 = wn * 64 + ni * 8 + 2 * q;    // 0..255
                size_t base = (c0 < 128) ? 0 : ((size_t)NQ * 128 - 128);
                atomicAdd(&Cout[base + (size_t)r0 * 128 + c0], acc[mi][ni][0]);
                atomicAdd(&Cout[base + (size_t)r0 * 128 + c0 + 1], acc[mi][ni][1]);
                atomicAdd(&Cout[base + (size_t)(r0 + 8) * 128 + c0], acc[mi][ni][2]);
                atomicAdd(&Cout[base + (size_t)(r0 + 8) * 128 + c0 + 1], acc[mi][ni][3]);
            }
        }
    }
}

// ---------------- K3: edge bias MLP + scatter-add onto scores (edge_index is int32) ----
__global__ void bias_kernel(const int* __restrict__ ei, const float* __restrict__ rbf,
                            const float* __restrict__ W1, const float* __restrict__ b1,
                            const float* __restrict__ W2, const float* __restrict__ b2) {
    __shared__ float sW1[EDIM * HID];
    __shared__ float sb1[HID], sW2[HID];
    __shared__ float sb2;
    for (int t = threadIdx.x; t < EDIM * HID; t += blockDim.x) sW1[t] = W1[t];
    if (threadIdx.x < HID) { sb1[threadIdx.x] = b1[threadIdx.x]; sW2[threadIdx.x] = W2[threadIdx.x]; }
    if (threadIdx.x == 0) sb2 = b2[0];
    __syncthreads();

    int e = blockIdx.x * blockDim.x + threadIdx.x;
    if (e >= EQ) return;

    float h[HID];
#pragma unroll
    for (int j = 0; j < HID; j++) h[j] = sb1[j];
    const float* r = rbf + (size_t)e * EDIM;
    for (int k = 0; k < EDIM; k++) {
        float rv = __ldg(&r[k]);
#pragma unroll
        for (int j = 0; j < HID; j++) h[j] = fmaf(rv, sW1[k * HID + j], h[j]);
    }
    float bias = sb2;
#pragma unroll
    for (int j = 0; j < HID; j++) {
        float x = h[j];
        float si = x / (1.f + __expf(-x));   // SiLU
        bias = fmaf(si, sW2[j], bias);
    }
    int i  = ei[e];
    int jn = ei[EQ + e];
    atomicAdd(&g_scores[(size_t)i * NQ + jn], bias);
}

// ---------------- K4: row softmax, register-resident ----------------
__global__ __launch_bounds__(256)
void softmax_kernel() {
    __shared__ float red[8];
    const int row = blockIdx.x, tid = threadIdx.x;
    const float4* src = (const float4*)(g_scores + (size_t)row * NQ);

    float4 v[8];
    float m = -1e30f;
#pragma unroll
    for (int i = 0; i < 8; i++) {
        v[i] = src[tid + i * 256];
        m = fmaxf(m, fmaxf(fmaxf(v[i].x, v[i].y), fmaxf(v[i].z, v[i].w)));
    }
#pragma unroll
    for (int o = 16; o; o >>= 1) m = fmaxf(m, __shfl_xor_sync(0xffffffffu, m, o));
    if ((tid & 31) == 0) red[tid >> 5] = m;
    __syncthreads();
    float bm = red[0];
#pragma unroll
    for (int w = 1; w < 8; w++) bm = fmaxf(bm, red[w]);
    __syncthreads();

    float sum = 0.f;
#pragma unroll
    for (int i = 0; i < 8; i++) {
        v[i].x = __expf(v[i].x - bm); v[i].y = __expf(v[i].y - bm);
        v[i].z = __expf(v[i].z - bm); v[i].w = __expf(v[i].w - bm);
        sum += v[i].x + v[i].y + v[i].z + v[i].w;
    }
#pragma unroll
    for (int o = 16; o; o >>= 1) sum += __shfl_xor_sync(0xffffffffu, sum, o);
    if ((tid & 31) == 0) red[tid >> 5] = sum;
    __syncthreads();
    float tot = 0.f;
#pragma unroll
    for (int w = 0; w < 8; w++) tot += red[w];
    const float inv = 1.f / tot;

    uint2* dst = (uint2*)(g_attn + (size_t)row * NQ);
#pragma unroll
    for (int i = 0; i < 8; i++) {
        __half2 lo = __floats2half2_rn(v[i].x * inv, v[i].y * inv);
        __half2 hi = __floats2half2_rn(v[i].z * inv, v[i].w * inv);
        uint2 o;
        o.x = *(unsigned*)&lo;
        o.y = *(unsigned*)&hi;
        dst[tid + i * 256] = o;
    }
}

// ---------------- launch ----------------
extern "C" void kernel_launch(void* const* d_in, const int* in_sizes, int n_in,
                              void* d_out, int out_size) {
    const float* mag   = (const float*)d_in[0];
    const float* phase = (const float*)d_in[1];
    const int*   ei    = (const int*)d_in[2];
    const float* rbf   = (const float*)d_in[3];
    const float* W1    = (const float*)d_in[4];
    const float* b1    = (const float*)d_in[5];
    const float* W2    = (const float*)d_in[6];
    const float* b2    = (const float*)d_in[7];
    float*       out   = (float*)d_out;

    const float inv_sqrt_d = 0.08838834764831843f;   // 1/sqrt(128)
    const int smem0 = 2 * (128 + 128) * TSTRIDE * (int)sizeof(__half);   // 73728
    const int smem1 = 2 * (128 + 256) * TSTRIDE * (int)sizeof(__half);   // 110592

    cudaFuncSetAttribute(gemm_kernel<0>, cudaFuncAttributeMaxDynamicSharedMemorySize, smem0);
    cudaFuncSetAttribute(gemm_kernel<1>, cudaFuncAttributeMaxDynamicSharedMemorySize, smem1);

    prep_kernel<<<(NQ * DQ) / 256, 256>>>(mag, phase, out);
    gemm_kernel<0><<<dim3(NQ / 128, NQ / 128), 256, smem0>>>(nullptr, inv_sqrt_d);
    bias_kernel<<<EQ / 256, 256>>>(ei, rbf, W1, b1, W2, b2);
    softmax_kernel<<<NQ, 256>>>();
    gemm_kernel<1><<<dim3(1, NQ / 128, 4), 256, smem1>>>(out, 1.0f);
}